// round 1
// baseline (speedup 1.0000x reference)
#include <cuda_runtime.h>
#include <math.h>

#define NB 16
#define NV 256
#define NR 1024
#define RMASK 1023
#define VMASK 255

// OS-CFAR intermediate (scratch): static device array (no allocations allowed).
__device__ float g_os[NB * NV * NR];

// Descending compare-and-swap: a keeps max, b keeps min.
#define CAS(a, b) do { float _hi = fmaxf(a, b); float _lo = fminf(a, b); (a) = _hi; (b) = _lo; } while (0)

// Batcher odd-even mergesort for 8 elements, descending (19 comparators).
__device__ __forceinline__ void sort8r(float& x0, float& x1, float& x2, float& x3,
                                       float& x4, float& x5, float& x6, float& x7) {
    // sort4 [x0..x3]
    CAS(x0, x1); CAS(x2, x3); CAS(x0, x2); CAS(x1, x3); CAS(x1, x2);
    // sort4 [x4..x7]
    CAS(x4, x5); CAS(x6, x7); CAS(x4, x6); CAS(x5, x7); CAS(x5, x6);
    // odd-even merge 4+4
    CAS(x0, x4); CAS(x2, x6); CAS(x2, x4);
    CAS(x1, x5); CAS(x3, x7); CAS(x3, x5);
    CAS(x1, x2); CAS(x3, x4); CAS(x5, x6);
}

// Kernel 1: per (b,v) row, compute os_result[r] = alpha * (8th largest of the
// 32-cell window {r-20..r-5} U {r+5..r+20}, circular mod 1024).
// M(p) = sorted (desc) top-8 of the 16 contiguous cells starting at p.
// Left half of window r is M(r-20); right half is M(r+5).
// 8th largest of union = min_i max(ML[i], MR[7-i])  (bitonic half-cleaner + min).
__global__ void __launch_bounds__(256) os_kernel(const float* __restrict__ data, float alpha) {
    __shared__ float row[NR];
    __shared__ float M[NR][9];   // 9-float stride: conflict-free scalar LDS

    const int t = threadIdx.x;
    const float* src = data + (size_t)blockIdx.x * NR;

#pragma unroll
    for (int i = 0; i < NR / 256; i++) row[t + 256 * i] = src[t + 256 * i];
    __syncthreads();

    // Phase 2: each thread builds 4 M-lists (positions t, t+256, t+512, t+768).
#pragma unroll
    for (int w = 0; w < 4; w++) {
        const int p = t + 256 * w;
        float a0 = row[p];
        float a1 = row[(p + 1) & RMASK];
        float a2 = row[(p + 2) & RMASK];
        float a3 = row[(p + 3) & RMASK];
        float a4 = row[(p + 4) & RMASK];
        float a5 = row[(p + 5) & RMASK];
        float a6 = row[(p + 6) & RMASK];
        float a7 = row[(p + 7) & RMASK];
        sort8r(a0, a1, a2, a3, a4, a5, a6, a7);

        float b0 = row[(p + 8)  & RMASK];
        float b1 = row[(p + 9)  & RMASK];
        float b2 = row[(p + 10) & RMASK];
        float b3 = row[(p + 11) & RMASK];
        float b4 = row[(p + 12) & RMASK];
        float b5 = row[(p + 13) & RMASK];
        float b6 = row[(p + 14) & RMASK];
        float b7 = row[(p + 15) & RMASK];
        sort8r(b0, b1, b2, b3, b4, b5, b6, b7);

        // Half-cleaner: top-8 of the 16 (bitonic "valley" sequence)
        float e0 = fmaxf(a0, b7), e1 = fmaxf(a1, b6), e2 = fmaxf(a2, b5), e3 = fmaxf(a3, b4);
        float e4 = fmaxf(a4, b3), e5 = fmaxf(a5, b2), e6 = fmaxf(a6, b1), e7 = fmaxf(a7, b0);
        // Bitonic merge -> fully sorted descending (12 comparators)
        CAS(e0, e4); CAS(e1, e5); CAS(e2, e6); CAS(e3, e7);
        CAS(e0, e2); CAS(e1, e3); CAS(e4, e6); CAS(e5, e7);
        CAS(e0, e1); CAS(e2, e3); CAS(e4, e5); CAS(e6, e7);

        float* Mp = M[p];
        Mp[0] = e0; Mp[1] = e1; Mp[2] = e2; Mp[3] = e3;
        Mp[4] = e4; Mp[5] = e5; Mp[6] = e6; Mp[7] = e7;
    }
    __syncthreads();

    // Phase 3: combine left/right sorted top-8 lists, take 8th largest.
    float* dst = g_os + (size_t)blockIdx.x * NR;
#pragma unroll
    for (int w = 0; w < 4; w++) {
        const int r = t + 256 * w;
        const float* A  = M[(r - 20) & RMASK];
        const float* Bp = M[(r + 5)  & RMASK];
        float m0 = fmaxf(A[0], Bp[7]);
        float m1 = fmaxf(A[1], Bp[6]);
        float m2 = fmaxf(A[2], Bp[5]);
        float m3 = fmaxf(A[3], Bp[4]);
        float m4 = fmaxf(A[4], Bp[3]);
        float m5 = fmaxf(A[5], Bp[2]);
        float m6 = fmaxf(A[6], Bp[1]);
        float m7 = fmaxf(A[7], Bp[0]);
        float mn = fminf(fminf(fminf(m0, m1), fminf(m2, m3)),
                         fminf(fminf(m4, m5), fminf(m6, m7)));
        dst[r] = alpha * mn;
    }
}

// Kernel 2: CA along V (circular mod 256): out[v] = (1/16) * sum_{|d| in 3..10} os[(v+d)%256].
// Block = (batch b, 32-wide r chunk); tile os[256][32] in smem.
__global__ void __launch_bounds__(256) ca_kernel(float* __restrict__ out) {
    __shared__ float tile[NV][32];
    const int b  = blockIdx.x >> 5;
    const int r0 = (blockIdx.x & 31) * 32;
    const int t  = threadIdx.x;

    const float* src = g_os + (size_t)b * NV * NR + r0;
#pragma unroll
    for (int i = 0; i < 32; i++) {
        int idx = t + 256 * i;                 // 0..8191
        int v = idx >> 5, rl = idx & 31;
        tile[v][rl] = src[(size_t)v * NR + rl];
    }
    __syncthreads();

    const int rl = t & 31;
    const int v0 = (t >> 5) * 32;              // 8 groups of 32 v's
    float* dst = out + (size_t)b * NV * NR + r0 + rl;
#pragma unroll 4
    for (int vi = 0; vi < 32; vi++) {
        const int v = v0 + vi;
        float s = 0.0f;
#pragma unroll
        for (int d = 3; d <= 10; d++) {
            s += tile[(v + d) & VMASK][rl];
            s += tile[(v - d) & VMASK][rl];
        }
        dst[(size_t)v * NR] = s * (1.0f / 16.0f);
    }
}

// ---------------- host: replicate the reference's alpha solve exactly ----------------

static double cfar_log_factorial(double n) {
    n += 1.0;
    if (n < 9.0) {
        double f = 1.0;
        int m = (int)(n + 0.5);
        for (int i = 2; i <= m; i++) f *= (double)i;
        return log(f);
    }
    return 0.5 * (log(2.0 * 3.14159265358979323846) - log(n))
         + n * (log(n + 1.0 / (12.0 * n - 1.0 / (10.0 * n))) - 1.0);
}

static double cfar_fun(int k, int n, double t, double pfa) {
    double s = 0.0;
    for (int j = n; j > n - k; j--) s += log((double)j + t);
    return cfar_log_factorial((double)n) - cfar_log_factorial((double)(n - k)) - s - log(pfa);
}

extern "C" void kernel_launch(void* const* d_in, const int* in_sizes, int n_in,
                              void* d_out, int out_size) {
    (void)in_sizes; (void)n_in; (void)out_size;
    const float* data = (const float*)d_in[0];
    float* out = (float*)d_out;

    // Bisect fun (monotone decreasing) on [1, 1e6] to machine precision.
    // Host-side, deterministic; runs only at capture time.
    double lo = 1.0, hi = 1.0e6;
    for (int it = 0; it < 200; it++) {
        double mid = 0.5 * (lo + hi);
        if (cfar_fun(24, 32, mid, 1.0e-5) > 0.0) lo = mid; else hi = mid;
    }
    float alpha = (float)sqrt(0.5 * (lo + hi));   // ~3.3679

    os_kernel<<<NB * NV, 256>>>(data, alpha);
    ca_kernel<<<NB * 32, 256>>>(out);
}

// round 2
// speedup vs baseline: 1.6057x; 1.6057x over previous
#include <cuda_runtime.h>
#include <cuda_fp16.h>
#include <math.h>

#define NB 16
#define NV 256
#define NR 1024
#define RMASK 1023
#define VMASK 255

// OS-CFAR intermediate (fp32 — avoids a second half-rounding before the CA sum).
__device__ float g_os[NB * NV * NR];

// Descending compare-and-swap on packed half2 (elementwise SIMD).
#define CAS2(a, b) do { __half2 _hi = __hmax2(a, b); __half2 _lo = __hmin2(a, b); (a) = _hi; (b) = _lo; } while (0)

// Batcher odd-even mergesort for 8 half2 lanes, descending (19 comparators).
__device__ __forceinline__ void sort8h(__half2& x0, __half2& x1, __half2& x2, __half2& x3,
                                       __half2& x4, __half2& x5, __half2& x6, __half2& x7) {
    CAS2(x0, x1); CAS2(x2, x3); CAS2(x0, x2); CAS2(x1, x3); CAS2(x1, x2);
    CAS2(x4, x5); CAS2(x6, x7); CAS2(x4, x6); CAS2(x5, x7); CAS2(x5, x6);
    CAS2(x0, x4); CAS2(x2, x6); CAS2(x2, x4);
    CAS2(x1, x5); CAS2(x3, x7); CAS2(x3, x5);
    CAS2(x1, x2); CAS2(x3, x4); CAS2(x5, x6);
}

// Kernel 1 (half2-packed, 2 (b,v)-rows per block):
//   L(p) = sorted-desc-8 of row[p..p+7]                  (phase A, computed ONCE per p)
//   M(p) = sorted-desc top-8 of row[p..p+15]             (phase B: halfclean(L(p),L(p+8)) + bitonic merge)
//   os(r) = alpha * min_i max(M(r-20)[i], M(r+5)[7-i])   (phase C: 8th largest of the 32-cell window)
// smem layout (dynamic, 69632 B): row2[1024] half2 | Ls[8][1024] half2 | Mm[8][1024] half2
__global__ void __launch_bounds__(256) os2_kernel(const float* __restrict__ data, float alpha) {
    extern __shared__ unsigned char sm[];
    __half2* row2 = (__half2*)sm;                        // 4096 B
    __half2* Ls   = (__half2*)(sm + 4096);               // 32768 B, Ls[c*1024 + p]
    __half2* Mm   = (__half2*)(sm + 4096 + 32768);       // 32768 B, Mm[c*1024 + p]

    const int t = threadIdx.x;
    const float* srcA = data + (size_t)(2 * blockIdx.x) * NR;
    const float* srcB = srcA + NR;

#pragma unroll
    for (int i = 0; i < 4; i++) {
        int r = t + 256 * i;
        row2[r] = __floats2half2_rn(srcA[r], srcB[r]);
    }
    __syncthreads();

    // Phase A: sorted-8 sublists L(p) for all p.
#pragma unroll
    for (int w = 0; w < 4; w++) {
        const int p = t + 256 * w;
        __half2 a0 = row2[p];
        __half2 a1 = row2[(p + 1) & RMASK];
        __half2 a2 = row2[(p + 2) & RMASK];
        __half2 a3 = row2[(p + 3) & RMASK];
        __half2 a4 = row2[(p + 4) & RMASK];
        __half2 a5 = row2[(p + 5) & RMASK];
        __half2 a6 = row2[(p + 6) & RMASK];
        __half2 a7 = row2[(p + 7) & RMASK];
        sort8h(a0, a1, a2, a3, a4, a5, a6, a7);
        Ls[0 * NR + p] = a0; Ls[1 * NR + p] = a1; Ls[2 * NR + p] = a2; Ls[3 * NR + p] = a3;
        Ls[4 * NR + p] = a4; Ls[5 * NR + p] = a5; Ls[6 * NR + p] = a6; Ls[7 * NR + p] = a7;
    }
    __syncthreads();

    // Phase B: M(p) = sorted top-8 of 16-run = halfclean(L(p), L(p+8)) + bitonic merge.
#pragma unroll
    for (int w = 0; w < 4; w++) {
        const int p = t + 256 * w;
        const int q = (p + 8) & RMASK;
        __half2 a0 = Ls[0 * NR + p], a1 = Ls[1 * NR + p], a2 = Ls[2 * NR + p], a3 = Ls[3 * NR + p];
        __half2 a4 = Ls[4 * NR + p], a5 = Ls[5 * NR + p], a6 = Ls[6 * NR + p], a7 = Ls[7 * NR + p];
        __half2 b0 = Ls[0 * NR + q], b1 = Ls[1 * NR + q], b2 = Ls[2 * NR + q], b3 = Ls[3 * NR + q];
        __half2 b4 = Ls[4 * NR + q], b5 = Ls[5 * NR + q], b6 = Ls[6 * NR + q], b7 = Ls[7 * NR + q];
        __half2 e0 = __hmax2(a0, b7), e1 = __hmax2(a1, b6), e2 = __hmax2(a2, b5), e3 = __hmax2(a3, b4);
        __half2 e4 = __hmax2(a4, b3), e5 = __hmax2(a5, b2), e6 = __hmax2(a6, b1), e7 = __hmax2(a7, b0);
        CAS2(e0, e4); CAS2(e1, e5); CAS2(e2, e6); CAS2(e3, e7);
        CAS2(e0, e2); CAS2(e1, e3); CAS2(e4, e6); CAS2(e5, e7);
        CAS2(e0, e1); CAS2(e2, e3); CAS2(e4, e5); CAS2(e6, e7);
        Mm[0 * NR + p] = e0; Mm[1 * NR + p] = e1; Mm[2 * NR + p] = e2; Mm[3 * NR + p] = e3;
        Mm[4 * NR + p] = e4; Mm[5 * NR + p] = e5; Mm[6 * NR + p] = e6; Mm[7 * NR + p] = e7;
    }
    __syncthreads();

    // Phase C: 8th largest of union of two sorted-8 lists, scale, store fp32.
    float* dstA = g_os + (size_t)(2 * blockIdx.x) * NR;
    float* dstB = dstA + NR;
#pragma unroll
    for (int w = 0; w < 4; w++) {
        const int r  = t + 256 * w;
        const int pa = (r - 20) & RMASK;
        const int pb = (r + 5)  & RMASK;
        __half2 m0 = __hmax2(Mm[0 * NR + pa], Mm[7 * NR + pb]);
        __half2 m1 = __hmax2(Mm[1 * NR + pa], Mm[6 * NR + pb]);
        __half2 m2 = __hmax2(Mm[2 * NR + pa], Mm[5 * NR + pb]);
        __half2 m3 = __hmax2(Mm[3 * NR + pa], Mm[4 * NR + pb]);
        __half2 m4 = __hmax2(Mm[4 * NR + pa], Mm[3 * NR + pb]);
        __half2 m5 = __hmax2(Mm[5 * NR + pa], Mm[2 * NR + pb]);
        __half2 m6 = __hmax2(Mm[6 * NR + pa], Mm[1 * NR + pb]);
        __half2 m7 = __hmax2(Mm[7 * NR + pa], Mm[0 * NR + pb]);
        __half2 mn = __hmin2(__hmin2(__hmin2(m0, m1), __hmin2(m2, m3)),
                             __hmin2(__hmin2(m4, m5), __hmin2(m6, m7)));
        dstA[r] = alpha * __low2float(mn);
        dstB[r] = alpha * __high2float(mn);
    }
}

// Kernel 2: CA along V via sliding box sums: out(v) = (box21(v) - box5(v)) / 16,
// box21 = sum_{d=-10..10}, box5 = sum_{d=-2..2} (circular mod 256).
// Block = (batch, 32-wide r chunk); each thread slides a 16-long v run.
__global__ void __launch_bounds__(512) ca_kernel(float* __restrict__ out) {
    __shared__ float tile[NV][32];
    const int b  = blockIdx.x >> 5;
    const int r0 = (blockIdx.x & 31) * 32;
    const int t  = threadIdx.x;

    const float* src = g_os + (size_t)b * NV * NR + r0;
#pragma unroll
    for (int i = 0; i < 16; i++) {
        int idx = t + 512 * i;
        int v = idx >> 5, rl = idx & 31;
        tile[v][rl] = src[(size_t)v * NR + rl];
    }
    __syncthreads();

    const int rl = t & 31;
    const int v0 = (t >> 5) * 16;      // 16 segments of 16 v's

    float box21 = 0.0f, box5 = 0.0f;
#pragma unroll
    for (int d = -10; d <= 10; d++) {
        float x = tile[(v0 + d) & VMASK][rl];
        box21 += x;
        if (d >= -2 && d <= 2) box5 += x;
    }

    float* dst = out + (size_t)b * NV * NR + r0 + rl;
#pragma unroll
    for (int vi = 0; vi < 16; vi++) {
        const int v = v0 + vi;
        dst[(size_t)v * NR] = (box21 - box5) * (1.0f / 16.0f);
        box21 += tile[(v + 11) & VMASK][rl] - tile[(v - 10) & VMASK][rl];
        box5  += tile[(v + 3)  & VMASK][rl] - tile[(v - 2)  & VMASK][rl];
    }
}

// ---------------- host: replicate the reference's alpha solve ----------------

static double cfar_log_factorial(double n) {
    n += 1.0;
    if (n < 9.0) {
        double f = 1.0;
        int m = (int)(n + 0.5);
        for (int i = 2; i <= m; i++) f *= (double)i;
        return log(f);
    }
    return 0.5 * (log(2.0 * 3.14159265358979323846) - log(n))
         + n * (log(n + 1.0 / (12.0 * n - 1.0 / (10.0 * n))) - 1.0);
}

static double cfar_fun(int k, int n, double t, double pfa) {
    double s = 0.0;
    for (int j = n; j > n - k; j--) s += log((double)j + t);
    return cfar_log_factorial((double)n) - cfar_log_factorial((double)(n - k)) - s - log(pfa);
}

extern "C" void kernel_launch(void* const* d_in, const int* in_sizes, int n_in,
                              void* d_out, int out_size) {
    (void)in_sizes; (void)n_in; (void)out_size;
    const float* data = (const float*)d_in[0];
    float* out = (float*)d_out;

    double lo = 1.0, hi = 1.0e6;
    for (int it = 0; it < 200; it++) {
        double mid = 0.5 * (lo + hi);
        if (cfar_fun(24, 32, mid, 1.0e-5) > 0.0) lo = mid; else hi = mid;
    }
    float alpha = (float)sqrt(0.5 * (lo + hi));   // ~3.3679

    const int OS_SMEM = 4096 + 32768 + 32768;    // 69632 B dynamic
    cudaFuncSetAttribute(os2_kernel, cudaFuncAttributeMaxDynamicSharedMemorySize, OS_SMEM);

    os2_kernel<<<NB * NV / 2, 256, OS_SMEM>>>(data, alpha);
    ca_kernel<<<NB * 32, 512>>>(out);
}

// round 3
// speedup vs baseline: 1.7369x; 1.0817x over previous
#include <cuda_runtime.h>
#include <cuda_fp16.h>
#include <math.h>

#define NB 16
#define NV 256
#define NR 1024
#define RMASK 1023
#define VMASK 255
#define CS 1056          // smem column stride (1024 + 32 wrap extension), even -> 8B-aligned pairs

// OS-CFAR intermediate: half2 packs two adjacent v-rows. 8.4 MB.
__device__ __half2 g_os2[(NB * NV / 2) * NR];

#define CAS2(a, b) do { __half2 _hi = __hmax2(a, b); __half2 _lo = __hmin2(a, b); (a) = _hi; (b) = _lo; } while (0)

// Batcher odd-even mergesort, 8 elems, descending (19 comparators).
__device__ __forceinline__ void sort8h(__half2* x) {
    CAS2(x[0], x[1]); CAS2(x[2], x[3]); CAS2(x[0], x[2]); CAS2(x[1], x[3]); CAS2(x[1], x[2]);
    CAS2(x[4], x[5]); CAS2(x[6], x[7]); CAS2(x[4], x[6]); CAS2(x[5], x[7]); CAS2(x[5], x[6]);
    CAS2(x[0], x[4]); CAS2(x[2], x[6]); CAS2(x[2], x[4]);
    CAS2(x[1], x[5]); CAS2(x[3], x[7]); CAS2(x[3], x[5]);
    CAS2(x[1], x[2]); CAS2(x[3], x[4]); CAS2(x[5], x[6]);
}

// M = sorted-desc top-8 of (sorted a) U (sorted b): half-cleaner + bitonic sort-8.
__device__ __forceinline__ void merge_top8(const __half2* a, const __half2* b, __half2* m) {
    m[0] = __hmax2(a[0], b[7]); m[1] = __hmax2(a[1], b[6]);
    m[2] = __hmax2(a[2], b[5]); m[3] = __hmax2(a[3], b[4]);
    m[4] = __hmax2(a[4], b[3]); m[5] = __hmax2(a[5], b[2]);
    m[6] = __hmax2(a[6], b[1]); m[7] = __hmax2(a[7], b[0]);
    CAS2(m[0], m[4]); CAS2(m[1], m[5]); CAS2(m[2], m[6]); CAS2(m[3], m[7]);
    CAS2(m[0], m[2]); CAS2(m[1], m[3]); CAS2(m[4], m[6]); CAS2(m[5], m[7]);
    CAS2(m[0], m[1]); CAS2(m[2], m[3]); CAS2(m[4], m[5]); CAS2(m[6], m[7]);
}

// 8th largest of union of two sorted-desc-8 lists = min_i max(A[i], B[7-i]).
__device__ __forceinline__ __half2 kth8(const __half2* a, const __half2* b) {
    __half2 m0 = __hmin2(__hmax2(a[0], b[7]), __hmax2(a[1], b[6]));
    __half2 m1 = __hmin2(__hmax2(a[2], b[5]), __hmax2(a[3], b[4]));
    __half2 m2 = __hmin2(__hmax2(a[4], b[3]), __hmax2(a[5], b[2]));
    __half2 m3 = __hmin2(__hmax2(a[6], b[1]), __hmax2(a[7], b[0]));
    return __hmin2(__hmin2(m0, m1), __hmin2(m2, m3));
}

// OS kernel: one block per v-row pair; 512 threads, thread t owns positions p=2t, 2t+1.
//   L(p) = sorted-8 of row[p..p+7]; M(p) = top-8 of row[p..p+15] = merge(L(p), L(p+8));
//   os(r) = alpha * 8th-largest( M(r-20) U M(r+5) ); thread t emits r = 2t+20, 2t+21.
// smem: row2ext[1040] | Ls[8][CS] | Mm[8][CS], all half2. Transposed tables: conflict-free.
__global__ void __launch_bounds__(512, 2) os3_kernel(const float* __restrict__ data, float alpha) {
    extern __shared__ unsigned char sm[];
    __half2* row2 = (__half2*)sm;                         // 1040 * 4 B
    __half2* Ls   = (__half2*)(sm + 4160);                // 8 * CS * 4 B
    __half2* Mm   = (__half2*)(sm + 4160 + 8 * CS * 4);

    const int t = threadIdx.x;
    const float2* srcA = (const float2*)(data + (size_t)(2 * blockIdx.x) * NR);
    const float2* srcB = (const float2*)(data + (size_t)(2 * blockIdx.x + 1) * NR);

    {   // load + pack: row2[2t], row2[2t+1]
        float2 fa = srcA[t], fb = srcB[t];
        row2[2 * t]     = __floats2half2_rn(fa.x, fb.x);
        row2[2 * t + 1] = __floats2half2_rn(fa.y, fb.y);
        if (t < 8) {  // wrap extension: row2[1024+i] = row2[i], i<16
            row2[1024 + 2 * t]     = __floats2half2_rn(fa.x, fb.x);
            row2[1024 + 2 * t + 1] = __floats2half2_rn(fa.y, fb.y);
        }
    }
    __syncthreads();

    // Phase A: build L(2t), L(2t+1) in registers; publish to smem.
    __half2 r[10];
    {
        const uint2* rp = (const uint2*)(row2 + 2 * t);   // 8B-aligned
#pragma unroll
        for (int k = 0; k < 5; k++) {
            uint2 q = rp[k];
            r[2 * k]     = *(__half2*)&q.x;
            r[2 * k + 1] = *(__half2*)&q.y;
        }
    }
    __half2 La[8], Lb[8];
#pragma unroll
    for (int i = 0; i < 8; i++) { La[i] = r[i]; Lb[i] = r[i + 1]; }
    sort8h(La);
    sort8h(Lb);
#pragma unroll
    for (int c = 0; c < 8; c++) {
        uint2 v; v.x = *(unsigned*)&La[c]; v.y = *(unsigned*)&Lb[c];
        *(uint2*)&Ls[c * CS + 2 * t] = v;
        if (t < 16) *(uint2*)&Ls[c * CS + 2 * t + 1024] = v;   // wrap dup (p<32)
    }
    __syncthreads();

    // Phase B: M(p) = merge(L(p) [regs], L(p+8) [smem]).
    __half2 xb[8], yb[8];
#pragma unroll
    for (int c = 0; c < 8; c++) {
        uint2 q = *(const uint2*)&Ls[c * CS + 2 * t + 8];
        xb[c] = *(__half2*)&q.x;   // L(2t+8)
        yb[c] = *(__half2*)&q.y;   // L(2t+9)
    }
    __half2 M0[8], M1[8];
    merge_top8(La, xb, M0);
    merge_top8(Lb, yb, M1);
#pragma unroll
    for (int c = 0; c < 8; c++) {
        uint2 v; v.x = *(unsigned*)&M0[c]; v.y = *(unsigned*)&M1[c];
        *(uint2*)&Mm[c * CS + 2 * t] = v;
        if (t < 16) *(uint2*)&Mm[c * CS + 2 * t + 1024] = v;
    }
    __syncthreads();

    // Phase C: out r = p+20 uses M(p) [regs] and M(p+25) [smem, scalar: odd offset].
    __half2 n0[8], n1[8];
#pragma unroll
    for (int c = 0; c < 8; c++) {
        n0[c] = Mm[c * CS + 2 * t + 25];
        n1[c] = Mm[c * CS + 2 * t + 26];
    }
    __half2 os0 = kth8(M0, n0);
    __half2 os1 = kth8(M1, n1);

    __half2* g2 = g_os2 + (size_t)blockIdx.x * NR;
    const int rr = (2 * t + 20) & RMASK;   // even; rr+1 adjacent
    __half2 h0 = __floats2half2_rn(alpha * __low2float(os0), alpha * __high2float(os0));
    __half2 h1 = __floats2half2_rn(alpha * __low2float(os1), alpha * __high2float(os1));
    uint2 o; o.x = *(unsigned*)&h0; o.y = *(unsigned*)&h1;
    *(uint2*)&g2[rr] = o;
}

// CA kernel: out(v) = (box21(v) - box5(v)) / 16 along v (circular mod 256).
// Block = (batch, 32-wide r chunk); tile unpacked to fp32 in smem.
__global__ void __launch_bounds__(512) ca_kernel(float* __restrict__ out) {
    __shared__ float tile[NV][32];
    const int b  = blockIdx.x >> 5;
    const int r0 = (blockIdx.x & 31) * 32;
    const int t  = threadIdx.x;

    const __half2* src = g_os2 + (size_t)b * (NV / 2) * NR + r0;
#pragma unroll
    for (int i = 0; i < 8; i++) {
        int idx = t + 512 * i;             // 0..4095
        int vp = idx >> 5, rl = idx & 31;
        __half2 v2 = src[(size_t)vp * NR + rl];
        tile[2 * vp][rl]     = __low2float(v2);
        tile[2 * vp + 1][rl] = __high2float(v2);
    }
    __syncthreads();

    const int rl = t & 31;
    const int v0 = (t >> 5) * 16;

    float box21 = 0.0f, box5 = 0.0f;
#pragma unroll
    for (int d = -10; d <= 10; d++) {
        float x = tile[(v0 + d) & VMASK][rl];
        box21 += x;
        if (d >= -2 && d <= 2) box5 += x;
    }

    float* dst = out + (size_t)b * NV * NR + r0 + rl;
#pragma unroll
    for (int vi = 0; vi < 16; vi++) {
        const int v = v0 + vi;
        dst[(size_t)v * NR] = (box21 - box5) * (1.0f / 16.0f);
        box21 += tile[(v + 11) & VMASK][rl] - tile[(v - 10) & VMASK][rl];
        box5  += tile[(v + 3)  & VMASK][rl] - tile[(v - 2)  & VMASK][rl];
    }
}

// ---------------- host: replicate the reference's alpha solve ----------------

static double cfar_log_factorial(double n) {
    n += 1.0;
    if (n < 9.0) {
        double f = 1.0;
        int m = (int)(n + 0.5);
        for (int i = 2; i <= m; i++) f *= (double)i;
        return log(f);
    }
    return 0.5 * (log(2.0 * 3.14159265358979323846) - log(n))
         + n * (log(n + 1.0 / (12.0 * n - 1.0 / (10.0 * n))) - 1.0);
}

static double cfar_fun(int k, int n, double t, double pfa) {
    double s = 0.0;
    for (int j = n; j > n - k; j--) s += log((double)j + t);
    return cfar_log_factorial((double)n) - cfar_log_factorial((double)(n - k)) - s - log(pfa);
}

extern "C" void kernel_launch(void* const* d_in, const int* in_sizes, int n_in,
                              void* d_out, int out_size) {
    (void)in_sizes; (void)n_in; (void)out_size;
    const float* data = (const float*)d_in[0];
    float* out = (float*)d_out;

    double lo = 1.0, hi = 1.0e6;
    for (int it = 0; it < 200; it++) {
        double mid = 0.5 * (lo + hi);
        if (cfar_fun(24, 32, mid, 1.0e-5) > 0.0) lo = mid; else hi = mid;
    }
    float alpha = (float)sqrt(0.5 * (lo + hi));   // ~3.3679

    const int OS_SMEM = 4160 + 2 * 8 * CS * 4;   // 71744 B
    cudaFuncSetAttribute(os3_kernel, cudaFuncAttributeMaxDynamicSharedMemorySize, OS_SMEM);

    os3_kernel<<<NB * NV / 2, 512, OS_SMEM>>>(data, alpha);
    ca_kernel<<<NB * 32, 512>>>(out);
}